// round 4
// baseline (speedup 1.0000x reference)
#include <cuda_runtime.h>
#include <math.h>

// Depthwise conv1d, K=7, 'same' padding, softmax over taps — fused, NO smem tile.
// x: (B, C, T) fp32; weight: (H, 1, 7); head for channel c is c % H (H=16).
// Each thread: 3 overlapping global float4 loads (L1 serves redundancy) -> 4 outputs.
// Block = 1024 contiguous elements = quarter of one T=4096 row (head uniform per block).

#define KSIZE 7
#define T_LEN 4096
#define THREADS 256
#define BLOCK_ELEMS (THREADS * 4)   // 1024

__global__ __launch_bounds__(THREADS)
void lconv1d_nosmem_kernel(const float* __restrict__ x,
                           const float* __restrict__ wraw,
                           float* __restrict__ out) {
    __shared__ float sw[KSIZE];

    const int row  = blockIdx.x >> 2;                       // b*C + c
    const int t    = (blockIdx.x & 3) * BLOCK_ELEMS + threadIdx.x * 4;
    const size_t base = (size_t)row * T_LEN;

    // Fused softmax over this row's head taps (threads 0..6).
    if (threadIdx.x < KSIZE) {
        const int h = row & 15;                             // C=1024 multiple of H=16
        float v[KSIZE];
        float m = -1e30f;
        #pragma unroll
        for (int k = 0; k < KSIZE; k++) {
            v[k] = __ldg(&wraw[h * KSIZE + k]);
            m = fmaxf(m, v[k]);
        }
        float sum = 0.f;
        #pragma unroll
        for (int k = 0; k < KSIZE; k++) sum += expf(v[k] - m);
        sw[threadIdx.x] = expf(v[threadIdx.x] - m) / sum;
    }

    // Three independent 16B-aligned loads; edges zero-padded ('same', PAD=3).
    const float4 b = *reinterpret_cast<const float4*>(x + base + t);
    float4 a, c;
    if (t > 0)          a = *reinterpret_cast<const float4*>(x + base + t - 4);
    else                a = make_float4(0.f, 0.f, 0.f, 0.f);
    if (t < T_LEN - 4)  c = *reinterpret_cast<const float4*>(x + base + t + 4);
    else                c = make_float4(0.f, 0.f, 0.f, 0.f);

    __syncthreads();
    const float w0 = sw[0], w1 = sw[1], w2 = sw[2], w3 = sw[3],
                w4 = sw[4], w5 = sw[5], w6 = sw[6];

    float4 r;
    r.x = w0*a.y + w1*a.z + w2*a.w + w3*b.x + w4*b.y + w5*b.z + w6*b.w;
    r.y = w0*a.z + w1*a.w + w2*b.x + w3*b.y + w4*b.z + w5*b.w + w6*c.x;
    r.z = w0*a.w + w1*b.x + w2*b.y + w3*b.z + w4*b.w + w5*c.x + w6*c.y;
    r.w = w0*b.x + w1*b.y + w2*b.z + w3*b.w + w4*c.x + w5*c.y + w6*c.z;

    *reinterpret_cast<float4*>(out + base + t) = r;
}

extern "C" void kernel_launch(void* const* d_in, const int* in_sizes, int n_in,
                              void* d_out, int out_size) {
    const float* x = (const float*)d_in[0];
    const float* w = (const float*)d_in[1];
    float* out = (float*)d_out;

    const int rows = in_sizes[0] / T_LEN;          // B*C = 16384
    const int blocks = rows * (T_LEN / BLOCK_ELEMS); // 65536

    lconv1d_nosmem_kernel<<<blocks, THREADS>>>(x, w, out);
}

// round 5
// speedup vs baseline: 1.0839x; 1.0839x over previous
#include <cuda_runtime.h>
#include <math.h>

// Depthwise conv1d, K=7, 'same' padding, softmax over taps — single fused kernel.
// x: (B, C, T) fp32; weight: (H, 1, 7); head for channel c is c % H (H=16).
// R2 tile structure (best DRAM%): TILE=2048, 8KB smem, MLP=2, register-reused
// middle chunk; softmax fused into block prologue (hidden under the LDGs).

#define KSIZE 7
#define TILE 2048
#define HALF (TILE / 2)
#define THREADS 256
#define SHIFT 4   // s[SHIFT + i] = x[t0 + i]; halo lives at s[1..3]
#define T_LEN 4096

__global__ __launch_bounds__(THREADS)
void lconv1d_fused_kernel(const float* __restrict__ x,
                          const float* __restrict__ wraw,
                          float* __restrict__ out) {
    __shared__ float s[SHIFT + TILE + 3];
    __shared__ float sw[KSIZE];

    const int row = blockIdx.y;               // b*C + c
    const int t0  = blockIdx.x * TILE;
    const size_t base = (size_t)row * T_LEN + t0;
    const int tid = threadIdx.x;
    const int p0 = tid * 4;
    const int p1 = p0 + HALF;

    // Two independent main-tile loads per thread (MLP=2), aligned STS.128.
    const float4 v0 = *reinterpret_cast<const float4*>(x + base + p0);
    const float4 v1 = *reinterpret_cast<const float4*>(x + base + p1);
    *reinterpret_cast<float4*>(&s[SHIFT + p0]) = v0;
    *reinterpret_cast<float4*>(&s[SHIFT + p1]) = v1;

    // Halos (3 left, 3 right) with zero padding at row boundaries.
    if (tid < 3) {
        s[1 + tid]            = (t0 > 0)            ? x[base - 3 + tid]    : 0.f;
        s[SHIFT + TILE + tid] = (t0 + TILE < T_LEN) ? x[base + TILE + tid] : 0.f;
    }

    // Fused softmax over this row's head taps (threads 0..6) — hides under LDGs.
    if (tid < KSIZE) {
        const int h = row & 15;               // C=1024 multiple of H=16
        float v[KSIZE];
        float m = -1e30f;
        #pragma unroll
        for (int k = 0; k < KSIZE; k++) {
            v[k] = __ldg(&wraw[h * KSIZE + k]);
            m = fmaxf(m, v[k]);
        }
        float sum = 0.f;
        #pragma unroll
        for (int k = 0; k < KSIZE; k++) sum += expf(v[k] - m);
        sw[tid] = expf(v[tid] - m) / sum;
    }

    __syncthreads();

    const float w0 = sw[0], w1 = sw[1], w2 = sw[2], w3 = sw[3],
                w4 = sw[4], w5 = sw[5], w6 = sw[6];

    // Chunk 0: outputs [p0 .. p0+3]. Middle float4 == v0 (register reuse).
    {
        const float4 a = *reinterpret_cast<const float4*>(&s[p0]);
        const float4 b = v0;
        const float4 c = *reinterpret_cast<const float4*>(&s[p0 + 8]);
        float4 r;
        r.x = w0*a.y + w1*a.z + w2*a.w + w3*b.x + w4*b.y + w5*b.z + w6*b.w;
        r.y = w0*a.z + w1*a.w + w2*b.x + w3*b.y + w4*b.z + w5*b.w + w6*c.x;
        r.z = w0*a.w + w1*b.x + w2*b.y + w3*b.z + w4*b.w + w5*c.x + w6*c.y;
        r.w = w0*b.x + w1*b.y + w2*b.z + w3*b.w + w4*c.x + w5*c.y + w6*c.z;
        *reinterpret_cast<float4*>(out + base + p0) = r;
    }

    // Chunk 1: outputs [p1 .. p1+3]. Middle float4 == v1.
    {
        const float4 a = *reinterpret_cast<const float4*>(&s[p1]);
        const float4 b = v1;
        const float4 c = *reinterpret_cast<const float4*>(&s[p1 + 8]);
        float4 r;
        r.x = w0*a.y + w1*a.z + w2*a.w + w3*b.x + w4*b.y + w5*b.z + w6*b.w;
        r.y = w0*a.z + w1*a.w + w2*b.x + w3*b.y + w4*b.z + w5*b.w + w6*c.x;
        r.z = w0*a.w + w1*b.x + w2*b.y + w3*b.z + w4*b.w + w5*c.x + w6*c.y;
        r.w = w0*b.x + w1*b.y + w2*b.z + w3*b.w + w4*c.x + w5*c.y + w6*c.z;
        *reinterpret_cast<float4*>(out + base + p1) = r;
    }
}

extern "C" void kernel_launch(void* const* d_in, const int* in_sizes, int n_in,
                              void* d_out, int out_size) {
    const float* x = (const float*)d_in[0];
    const float* w = (const float*)d_in[1];
    float* out = (float*)d_out;

    const int rows = in_sizes[0] / T_LEN;   // B*C = 16384

    dim3 grid(T_LEN / TILE, rows);          // (2, 16384)
    lconv1d_fused_kernel<<<grid, THREADS>>>(x, w, out);
}